// round 2
// baseline (speedup 1.0000x reference)
#include <cuda_runtime.h>

#define NP    16384
#define CIN   128
#define COUT  256
#define KK    20
#define WCOLS 512
#define QPB   8
#define KTILE 2048

// ---- scratch (no allocations allowed: __device__ globals) ----
__device__ float4 g_cand[NP];
__device__ int    g_knn[NP * KK];
__device__ float  g_W2[CIN * WCOLS];
__device__ float  g_AB[(size_t)NP * WCOLS];   // [:,0:256)=A(+bias), [:,256:512)=B
__device__ float  g_sel[(size_t)NP * COUT];   // max_k (or min_k if gamma<0) of A+B
__device__ float  g_sum[COUT];
__device__ float  g_sumsq[COUT];
__device__ float  g_scale[COUT];
__device__ float  g_shift[COUT];

// ---- prep: pack candidates {x,y,z,|p|^2/2}, rearrange W to [128,512], zero stats ----
__global__ void prep_kernel(const float* __restrict__ pos, const float* __restrict__ W) {
    int t = blockIdx.x * blockDim.x + threadIdx.x;
    if (t < NP) {
        float x = pos[3*t+0], y = pos[3*t+1], z = pos[3*t+2];
        g_cand[t] = make_float4(x, y, z, 0.5f*(x*x + y*y + z*z));
    }
    if (t < CIN * WCOLS) {
        int kk = t >> 9;
        int c  = t & 511;
        g_W2[t] = (c < COUT) ? W[kk*COUT + c] : W[(kk + CIN)*COUT + (c - COUT)];
    }
    if (t < COUT) { g_sum[t] = 0.0f; g_sumsq[t] = 0.0f; }
}

// ---- exact brute-force KNN: one query per lane, candidates tiled through smem ----
// score s_j = p_i . p_j - |p_j|^2/2 ; maximize s  <=>  minimize squared distance.
// Pass 1: keep top-21 scores (sorted 21-reg list, branchless merge-insert).
// thr = 21st best => exactly the top-20 are strictly > thr (generic case).
// Pass 2: collect indices with s > thr (neighbor ORDER is irrelevant: max-pool).
// Fallback: fill remaining slots with s == thr by ascending index (stable ties).
__global__ void knn_kernel() {
    __shared__ float4 tile[KTILE];
    const int q = blockIdx.x * blockDim.x + threadIdx.x;
    const float4 me = g_cand[q];
    const float NEG = -3.0e38f;
    float ss[21];
#pragma unroll
    for (int t = 0; t < 21; t++) ss[t] = NEG;

    for (int tb = 0; tb < NP; tb += KTILE) {
        __syncthreads();
        for (int l = threadIdx.x; l < KTILE; l += blockDim.x) tile[l] = g_cand[tb + l];
        __syncthreads();
#pragma unroll 4
        for (int j = 0; j < KTILE; j++) {
            float4 c = tile[j];
            float s = fmaf(me.x, c.x, fmaf(me.y, c.y, fmaf(me.z, c.z, -c.w)));
            if (s > ss[0]) {
                if (tb + j != q) {
                    // sorted ascending merge-insert dropping current min; 2 FMNMX/slot
#pragma unroll
                    for (int t = 0; t < 20; t++) ss[t] = fmaxf(ss[t], fminf(s, ss[t+1]));
                    ss[20] = fmaxf(ss[20], s);
                }
            }
        }
    }
    const float thr = ss[0];
    int cnt = 0;
    for (int tb = 0; tb < NP; tb += KTILE) {
        __syncthreads();
        for (int l = threadIdx.x; l < KTILE; l += blockDim.x) tile[l] = g_cand[tb + l];
        __syncthreads();
#pragma unroll 4
        for (int j = 0; j < KTILE; j++) {
            float4 c = tile[j];
            float s = fmaf(me.x, c.x, fmaf(me.y, c.y, fmaf(me.z, c.z, -c.w)));
            if (s > thr && (tb + j) != q && cnt < KK) {
                g_knn[q*KK + cnt] = tb + j;
                cnt++;
            }
        }
    }
    if (cnt < KK) {  // exact ties at threshold: essentially never with random floats
        for (int j = 0; j < NP && cnt < KK; j++) {
            if (j == q) continue;
            float4 c = g_cand[j];
            float s = fmaf(me.x, c.x, fmaf(me.y, c.y, fmaf(me.z, c.z, -c.w)));
            if (s == thr) { g_knn[q*KK + cnt] = j; cnt++; }
        }
    }
}

// ---- SGEMM: AB[16384,512] = X[16384,128] @ W2[128,512]  (+bias on cols<256) ----
// BM=BN=128, BK=8, 256 threads, 8x8 micro-tile.
__global__ void gemm_kernel(const float* __restrict__ X, const float* __restrict__ bias) {
    __shared__ float As[8][128];
    __shared__ float Bs[8][128];
    const int tid = threadIdx.x;
    const int m0 = blockIdx.y * 128;
    const int n0 = blockIdx.x * 128;
    const int tx = tid & 15;
    const int ty = tid >> 4;
    const int lam = tid >> 1;          // A-load row 0..127
    const int lak = (tid & 1) * 4;     // A-load col 0|4
    const int lbr = tid >> 5;          // B-load row 0..7
    const int lbc = (tid & 31) * 4;    // B-load col 0..124

    float acc[8][8];
#pragma unroll
    for (int i = 0; i < 8; i++)
#pragma unroll
        for (int j = 0; j < 8; j++) acc[i][j] = 0.0f;

    for (int kb = 0; kb < CIN; kb += 8) {
        float4 av = *(const float4*)&X[(size_t)(m0 + lam)*CIN + kb + lak];
        float4 bv = *(const float4*)&g_W2[(kb + lbr)*WCOLS + n0 + lbc];
        __syncthreads();
        As[lak+0][lam] = av.x;
        As[lak+1][lam] = av.y;
        As[lak+2][lam] = av.z;
        As[lak+3][lam] = av.w;
        *(float4*)&Bs[lbr][lbc] = bv;
        __syncthreads();
#pragma unroll
        for (int k = 0; k < 8; k++) {
            float a[8], bb[8];
            *(float4*)&a[0]  = *(const float4*)&As[k][ty*8];
            *(float4*)&a[4]  = *(const float4*)&As[k][ty*8 + 4];
            *(float4*)&bb[0] = *(const float4*)&Bs[k][tx*8];
            *(float4*)&bb[4] = *(const float4*)&Bs[k][tx*8 + 4];
#pragma unroll
            for (int i = 0; i < 8; i++)
#pragma unroll
                for (int j = 0; j < 8; j++)
                    acc[i][j] = fmaf(a[i], bb[j], acc[i][j]);
        }
    }
    const bool addb = (n0 < COUT);
#pragma unroll
    for (int i = 0; i < 8; i++) {
        int row = m0 + ty*8 + i;
#pragma unroll
        for (int j = 0; j < 8; j += 4) {
            int col = n0 + tx*8 + j;
            float4 v;
            v.x = acc[i][j+0] + (addb ? bias[col+0] : 0.0f);
            v.y = acc[i][j+1] + (addb ? bias[col+1] : 0.0f);
            v.z = acc[i][j+2] + (addb ? bias[col+2] : 0.0f);
            v.w = acc[i][j+3] + (addb ? bias[col+3] : 0.0f);
            *(float4*)&g_AB[(size_t)row*WCOLS + col] = v;
        }
    }
}

// ---- fused edge pass: per (i,c) max/min over neighbors + channel sum/sumsq ----
// BN+LeakyReLU are monotone affine per channel (scale sign = gamma sign), so
// max_k commutes with the epilogue: only the selected extreme needs normalizing.
__global__ void edge_kernel(const float* __restrict__ gamma) {
    const int c  = threadIdx.x;           // channel 0..255
    const int i0 = blockIdx.x * QPB;
    const bool useMax = (gamma[c] >= 0.0f);
    float psum = 0.0f, psumsq = 0.0f;
    for (int g = 0; g < QPB; g++) {
        const int i = i0 + g;
        const float a = g_AB[(size_t)i*WCOLS + c];
        float best = useMax ? -3.0e38f : 3.0e38f;
#pragma unroll
        for (int k = 0; k < KK; k++) {
            int j = g_knn[i*KK + k];
            float h = a + g_AB[(size_t)j*WCOLS + COUT + c];
            psum += h;
            psumsq = fmaf(h, h, psumsq);
            best = useMax ? fmaxf(best, h) : fminf(best, h);
        }
        g_sel[(size_t)i*COUT + c] = best;
    }
    atomicAdd(&g_sum[c], psum);
    atomicAdd(&g_sumsq[c], psumsq);
}

// ---- BN stats -> per-channel scale/shift ----
__global__ void finalize_kernel(const float* __restrict__ gamma, const float* __restrict__ beta) {
    int c = threadIdx.x;
    const float inv = 1.0f / (float)(NP * KK);
    float m  = g_sum[c] * inv;
    float v  = g_sumsq[c] * inv - m*m;
    float sc = gamma[c] * rsqrtf(v + 1e-5f);
    g_scale[c] = sc;
    g_shift[c] = beta[c] - m*sc;
}

// ---- epilogue: normalize selected extreme + LeakyReLU ----
__global__ void out_kernel(float* __restrict__ out) {
    int t = blockIdx.x * blockDim.x + threadIdx.x;
    int c = t & (COUT - 1);
    float h = fmaf(g_sel[t], g_scale[c], g_shift[c]);
    out[t] = (h >= 0.0f) ? h : 0.2f*h;
}

extern "C" void kernel_launch(void* const* d_in, const int* in_sizes, int n_in,
                              void* d_out, int out_size) {
    const float* pos   = (const float*)d_in[0];
    const float* x     = (const float*)d_in[1];
    const float* W     = (const float*)d_in[2];
    const float* b     = (const float*)d_in[3];
    const float* gamma = (const float*)d_in[4];
    const float* beta  = (const float*)d_in[5];
    float* out = (float*)d_out;

    prep_kernel<<<256, 256>>>(pos, W);                 // 65536 threads cover all prep
    knn_kernel<<<NP / 64, 64>>>();                     // 256 blocks x 64 thr, 1 query/lane
    gemm_kernel<<<dim3(WCOLS / 128, NP / 128), 256>>>(x, b);
    edge_kernel<<<NP / QPB, 256>>>(gamma);
    finalize_kernel<<<1, COUT>>>(gamma, beta);
    out_kernel<<<(NP * COUT) / 256, 256>>>(out);
}

// round 3
// speedup vs baseline: 1.0800x; 1.0800x over previous
#include <cuda_runtime.h>

#define NP     16384
#define CIN    128
#define COUT   256
#define KK     20
#define WCOLS  512
#define QPB    8
#define KTP    1024      /* pairs per knn smem tile -> 2048 candidates, 32KB */

// ---- scratch (no allocations allowed: __device__ globals) ----
__device__ float4 g_cand[NP];          // {x,y,z,|p|^2/2}
__device__ float4 g_A[NP/2];           // pair-SoA {x0,x1,y0,y1}
__device__ float4 g_B[NP/2];           // pair-SoA {z0,z1,-w0,-w1}
__device__ int    g_knn[NP * KK];
__device__ float  g_W2[CIN * WCOLS];
__device__ float  g_AB[(size_t)NP * WCOLS];   // [:,0:256)=A(+bias), [:,256:512)=B
__device__ float  g_sel[(size_t)NP * COUT];
__device__ double g_sumD[COUT];
__device__ double g_sumsqD[COUT];
__device__ float  g_scale[COUT];
__device__ float  g_shift[COUT];

// ---------- packed f32x2 helpers ----------
__device__ __forceinline__ unsigned long long ffma2(unsigned long long a,
                                                    unsigned long long b,
                                                    unsigned long long c) {
    unsigned long long d;
    asm("fma.rn.f32x2 %0, %1, %2, %3;" : "=l"(d) : "l"(a), "l"(b), "l"(c));
    return d;
}
__device__ __forceinline__ unsigned long long bcast2(float x) {
    unsigned long long r;
    asm("mov.b64 %0, {%1, %1};" : "=l"(r) : "f"(x));
    return r;
}
__device__ __forceinline__ void unpack2(unsigned long long v, float& lo, float& hi) {
    asm("mov.b64 {%0, %1}, %2;" : "=f"(lo), "=f"(hi) : "l"(v));
}
__device__ __forceinline__ unsigned long long d_as_ll(double d) {
    return __double_as_longlong(d);
}

// ---- prep: candidates (AoS + pair-SoA), W rearrange, stat zeroing ----
__global__ void prep_kernel(const float* __restrict__ pos, const float* __restrict__ W) {
    int t = blockIdx.x * blockDim.x + threadIdx.x;
    if (t < NP) {
        float x = pos[3*t+0], y = pos[3*t+1], z = pos[3*t+2];
        g_cand[t] = make_float4(x, y, z, 0.5f*(x*x + y*y + z*z));
    }
    if (t < NP/2) {
        int j0 = 2*t, j1 = 2*t + 1;
        float x0 = pos[3*j0+0], y0 = pos[3*j0+1], z0 = pos[3*j0+2];
        float x1 = pos[3*j1+0], y1 = pos[3*j1+1], z1 = pos[3*j1+2];
        float w0 = 0.5f*(x0*x0 + y0*y0 + z0*z0);
        float w1 = 0.5f*(x1*x1 + y1*y1 + z1*z1);
        g_A[t] = make_float4(x0, x1, y0, y1);
        g_B[t] = make_float4(z0, z1, -w0, -w1);
    }
    if (t < CIN * WCOLS) {
        int kk = t >> 9;
        int c  = t & 511;
        g_W2[t] = (c < COUT) ? W[kk*COUT + c] : W[(kk + CIN)*COUT + (c - COUT)];
    }
    if (t < COUT) { g_sumD[t] = 0.0; g_sumsqD[t] = 0.0; }
}

// ---- exact brute-force KNN, query-per-lane ----
// score s_j = p_i.p_j - |p_j|^2/2 ; maximize s <=> minimize distance.
// Group-of-8 max screening behind warp-uniform branches (__any_sync/__ballot_sync)
// so the 42-FMNMX sorted merge never gets if-converted into the hot path.
__global__ void knn_kernel() {
    __shared__ double2 tA[KTP];
    __shared__ double2 tB[KTP];
    const int q = blockIdx.x * blockDim.x + threadIdx.x;
    const float4 me = g_cand[q];
    const unsigned long long mx = bcast2(me.x);
    const unsigned long long my = bcast2(me.y);
    const unsigned long long mz = bcast2(me.z);
    const float NEG = -3.0e38f;
    const unsigned FULL = 0xffffffffu;

    float ss[21];
#pragma unroll
    for (int t = 0; t < 21; t++) ss[t] = NEG;

    // ---------------- pass 1: find 21st-best score ----------------
    for (int pb = 0; pb < NP/2; pb += KTP) {
        __syncthreads();
        for (int l = threadIdx.x; l < KTP; l += blockDim.x) {
            tA[l] = ((const double2*)g_A)[pb + l];
            tB[l] = ((const double2*)g_B)[pb + l];
        }
        __syncthreads();
        for (int g = 0; g < KTP; g += 4) {           // 4 pairs = 8 candidates
            float s[8];
#pragma unroll
            for (int p = 0; p < 4; p++) {
                double2 a = tA[g + p];
                double2 b = tB[g + p];
                unsigned long long t0 = ffma2(mz, d_as_ll(b.x), d_as_ll(b.y)); // z*mz - w
                t0 = ffma2(my, d_as_ll(a.y), t0);
                t0 = ffma2(mx, d_as_ll(a.x), t0);
                unpack2(t0, s[2*p], s[2*p+1]);
            }
            float gm = fmaxf(fmaxf(fmaxf(s[0], s[1]), fmaxf(s[2], s[3])),
                             fmaxf(fmaxf(s[4], s[5]), fmaxf(s[6], s[7])));
            if (__any_sync(FULL, gm > ss[0])) {      // warp-uniform rare branch
                const int jbase = 2*(pb + g);
#pragma unroll
                for (int u = 0; u < 8; u++) {
                    bool ins = (s[u] > ss[0]) && (jbase + u != q);
                    if (__ballot_sync(FULL, ins)) {  // warp-uniform rare branch
                        float sv = ins ? s[u] : NEG; // no-op merge for others
#pragma unroll
                        for (int t = 0; t < 20; t++)
                            ss[t] = fmaxf(ss[t], fminf(sv, ss[t+1]));
                        ss[20] = fmaxf(ss[20], sv);
                    }
                }
            }
        }
    }

    // ---------------- pass 2: collect indices strictly above threshold ----------------
    const float thr = ss[0];
    int cnt = 0;
    for (int pb = 0; pb < NP/2; pb += KTP) {
        __syncthreads();
        for (int l = threadIdx.x; l < KTP; l += blockDim.x) {
            tA[l] = ((const double2*)g_A)[pb + l];
            tB[l] = ((const double2*)g_B)[pb + l];
        }
        __syncthreads();
        for (int g = 0; g < KTP; g += 4) {
            float s[8];
#pragma unroll
            for (int p = 0; p < 4; p++) {
                double2 a = tA[g + p];
                double2 b = tB[g + p];
                unsigned long long t0 = ffma2(mz, d_as_ll(b.x), d_as_ll(b.y));
                t0 = ffma2(my, d_as_ll(a.y), t0);
                t0 = ffma2(mx, d_as_ll(a.x), t0);
                unpack2(t0, s[2*p], s[2*p+1]);
            }
            float gm = fmaxf(fmaxf(fmaxf(s[0], s[1]), fmaxf(s[2], s[3])),
                             fmaxf(fmaxf(s[4], s[5]), fmaxf(s[6], s[7])));
            if (__any_sync(FULL, gm > thr)) {
                const int jbase = 2*(pb + g);
#pragma unroll
                for (int u = 0; u < 8; u++) {
                    int j = jbase + u;
                    if (s[u] > thr && j != q && cnt < KK) {   // cheap predicated store
                        g_knn[q*KK + cnt] = j;
                        cnt++;
                    }
                }
            }
        }
    }
    if (cnt < KK) {  // exact ties at threshold: essentially never with random floats
        for (int j = 0; j < NP && cnt < KK; j++) {
            if (j == q) continue;
            float4 c = g_cand[j];
            float sv = fmaf(me.x, c.x, fmaf(me.y, c.y, fmaf(me.z, c.z, -c.w)));
            if (sv == thr) { g_knn[q*KK + cnt] = j; cnt++; }
        }
    }
}

// ---- SGEMM: AB[16384,512] = X[16384,128] @ W2[128,512]  (+bias on cols<256) ----
__global__ void gemm_kernel(const float* __restrict__ X, const float* __restrict__ bias) {
    __shared__ float As[8][128];
    __shared__ float Bs[8][128];
    const int tid = threadIdx.x;
    const int m0 = blockIdx.y * 128;
    const int n0 = blockIdx.x * 128;
    const int tx = tid & 15;
    const int ty = tid >> 4;
    const int lam = tid >> 1;
    const int lak = (tid & 1) * 4;
    const int lbr = tid >> 5;
    const int lbc = (tid & 31) * 4;

    float acc[8][8];
#pragma unroll
    for (int i = 0; i < 8; i++)
#pragma unroll
        for (int j = 0; j < 8; j++) acc[i][j] = 0.0f;

    for (int kb = 0; kb < CIN; kb += 8) {
        float4 av = *(const float4*)&X[(size_t)(m0 + lam)*CIN + kb + lak];
        float4 bv = *(const float4*)&g_W2[(kb + lbr)*WCOLS + n0 + lbc];
        __syncthreads();
        As[lak+0][lam] = av.x;
        As[lak+1][lam] = av.y;
        As[lak+2][lam] = av.z;
        As[lak+3][lam] = av.w;
        *(float4*)&Bs[lbr][lbc] = bv;
        __syncthreads();
#pragma unroll
        for (int k = 0; k < 8; k++) {
            float a[8], bb[8];
            *(float4*)&a[0]  = *(const float4*)&As[k][ty*8];
            *(float4*)&a[4]  = *(const float4*)&As[k][ty*8 + 4];
            *(float4*)&bb[0] = *(const float4*)&Bs[k][tx*8];
            *(float4*)&bb[4] = *(const float4*)&Bs[k][tx*8 + 4];
#pragma unroll
            for (int i = 0; i < 8; i++)
#pragma unroll
                for (int j = 0; j < 8; j++)
                    acc[i][j] = fmaf(a[i], bb[j], acc[i][j]);
        }
    }
    const bool addb = (n0 < COUT);
#pragma unroll
    for (int i = 0; i < 8; i++) {
        int row = m0 + ty*8 + i;
#pragma unroll
        for (int j = 0; j < 8; j += 4) {
            int col = n0 + tx*8 + j;
            float4 v;
            v.x = acc[i][j+0] + (addb ? bias[col+0] : 0.0f);
            v.y = acc[i][j+1] + (addb ? bias[col+1] : 0.0f);
            v.z = acc[i][j+2] + (addb ? bias[col+2] : 0.0f);
            v.w = acc[i][j+3] + (addb ? bias[col+3] : 0.0f);
            *(float4*)&g_AB[(size_t)row*WCOLS + col] = v;
        }
    }
}

// ---- fused edge pass: per (i,c) extreme over neighbors + channel sum/sumsq ----
__global__ void edge_kernel(const float* __restrict__ gamma) {
    const int c  = threadIdx.x;
    const int i0 = blockIdx.x * QPB;
    const bool useMax = (gamma[c] >= 0.0f);
    float psum = 0.0f, psumsq = 0.0f;
    for (int g = 0; g < QPB; g++) {
        const int i = i0 + g;
        const float a = g_AB[(size_t)i*WCOLS + c];
        float best = useMax ? -3.0e38f : 3.0e38f;
#pragma unroll
        for (int k = 0; k < KK; k++) {
            int j = g_knn[i*KK + k];
            float h = a + g_AB[(size_t)j*WCOLS + COUT + c];
            psum += h;
            psumsq = fmaf(h, h, psumsq);
            best = useMax ? fmaxf(best, h) : fminf(best, h);
        }
        g_sel[(size_t)i*COUT + c] = best;
    }
    atomicAdd(&g_sumD[c], (double)psum);
    atomicAdd(&g_sumsqD[c], (double)psumsq);
}

// ---- BN stats -> per-channel scale/shift ----
__global__ void finalize_kernel(const float* __restrict__ gamma, const float* __restrict__ beta) {
    int c = threadIdx.x;
    const double inv = 1.0 / (double)(NP * KK);
    double m  = g_sumD[c] * inv;
    double v  = g_sumsqD[c] * inv - m*m;
    float sc = gamma[c] * rsqrtf((float)v + 1e-5f);
    g_scale[c] = sc;
    g_shift[c] = beta[c] - (float)m * sc;
}

// ---- epilogue: normalize selected extreme + LeakyReLU ----
__global__ void out_kernel(float* __restrict__ out) {
    int t = blockIdx.x * blockDim.x + threadIdx.x;
    int c = t & (COUT - 1);
    float h = fmaf(g_sel[t], g_scale[c], g_shift[c]);
    out[t] = (h >= 0.0f) ? h : 0.2f*h;
}

extern "C" void kernel_launch(void* const* d_in, const int* in_sizes, int n_in,
                              void* d_out, int out_size) {
    const float* pos   = (const float*)d_in[0];
    const float* x     = (const float*)d_in[1];
    const float* W     = (const float*)d_in[2];
    const float* b     = (const float*)d_in[3];
    const float* gamma = (const float*)d_in[4];
    const float* beta  = (const float*)d_in[5];
    float* out = (float*)d_out;

    prep_kernel<<<256, 256>>>(pos, W);
    knn_kernel<<<NP / 64, 64>>>();
    gemm_kernel<<<dim3(WCOLS / 128, NP / 128), 256>>>(x, b);
    edge_kernel<<<NP / QPB, 256>>>(gamma);
    finalize_kernel<<<1, COUT>>>(gamma, beta);
    out_kernel<<<(NP * COUT) / 256, 256>>>(out);
}

// round 4
// speedup vs baseline: 2.8364x; 2.6263x over previous
#include <cuda_runtime.h>

#define NP     16384
#define CIN    128
#define COUT   256
#define KK     20
#define WCOLS  512
#define QPB    8
#define KTP    1024      /* pairs per knn smem tile -> 2048 candidates, 32KB */
#define CAP    1024      /* survivor buffer entries per query */

// ---- scratch (no allocations allowed: __device__ globals) ----
__device__ float4 g_cand[NP];          // {x,y,z,|p|^2/2}
__device__ float4 g_A[NP/2];           // pair-SoA {x0,x1,y0,y1}
__device__ float4 g_B[NP/2];           // pair-SoA {z0,z1,-w0,-w1}
__device__ float  g_thr1[NP];          // exact 21st-best score among first 2048 cands
__device__ unsigned long long g_buf[(size_t)CAP * NP];  // survivor (score<<32|idx), lane-interleaved
__device__ int    g_knn[NP * KK];
__device__ float  g_W2[CIN * WCOLS];
__device__ float  g_AB[(size_t)NP * WCOLS];   // [:,0:256)=A(+bias), [:,256:512)=B
__device__ float  g_sel[(size_t)NP * COUT];
__device__ double g_sumD[COUT];
__device__ double g_sumsqD[COUT];
__device__ float  g_scale[COUT];
__device__ float  g_shift[COUT];

// ---------- packed f32x2 helpers ----------
__device__ __forceinline__ unsigned long long ffma2(unsigned long long a,
                                                    unsigned long long b,
                                                    unsigned long long c) {
    unsigned long long d;
    asm("fma.rn.f32x2 %0, %1, %2, %3;" : "=l"(d) : "l"(a), "l"(b), "l"(c));
    return d;
}
__device__ __forceinline__ unsigned long long bcast2(float x) {
    unsigned long long r;
    asm("mov.b64 %0, {%1, %1};" : "=l"(r) : "f"(x));
    return r;
}
__device__ __forceinline__ void unpack2(unsigned long long v, float& lo, float& hi) {
    asm("mov.b64 {%0, %1}, %2;" : "=f"(lo), "=f"(hi) : "l"(v));
}
__device__ __forceinline__ unsigned long long d_as_ll(double d) {
    return __double_as_longlong(d);
}

// sorted-ascending 21-slot merge-insert (drops current min); branchless, ILP depth 2
__device__ __forceinline__ void merge21(float (&ss)[21], float sv) {
#pragma unroll
    for (int t = 0; t < 20; t++) ss[t] = fmaxf(ss[t], fminf(sv, ss[t+1]));
    ss[20] = fmaxf(ss[20], sv);
}

// 8 scores (4 packed pairs) from smem tiles
__device__ __forceinline__ void score8(float* s, const double2* tA, const double2* tB, int p,
                                       unsigned long long mx, unsigned long long my,
                                       unsigned long long mz) {
#pragma unroll
    for (int w = 0; w < 4; w++) {
        double2 a = tA[p + w];
        double2 b = tB[p + w];
        unsigned long long t0 = ffma2(mz, d_as_ll(b.x), d_as_ll(b.y));  // z*mz - w
        t0 = ffma2(my, d_as_ll(a.y), t0);
        t0 = ffma2(mx, d_as_ll(a.x), t0);
        unpack2(t0, s[2*w], s[2*w+1]);
    }
}

// ---- prep: candidates (AoS + pair-SoA), W rearrange, stat zeroing ----
__global__ void prep_kernel(const float* __restrict__ pos, const float* __restrict__ W) {
    int t = blockIdx.x * blockDim.x + threadIdx.x;
    if (t < NP) {
        float x = pos[3*t+0], y = pos[3*t+1], z = pos[3*t+2];
        g_cand[t] = make_float4(x, y, z, 0.5f*(x*x + y*y + z*z));
    }
    if (t < NP/2) {
        int j0 = 2*t, j1 = 2*t + 1;
        float x0 = pos[3*j0+0], y0 = pos[3*j0+1], z0 = pos[3*j0+2];
        float x1 = pos[3*j1+0], y1 = pos[3*j1+1], z1 = pos[3*j1+2];
        float w0 = 0.5f*(x0*x0 + y0*y0 + z0*z0);
        float w1 = 0.5f*(x1*x1 + y1*y1 + z1*z1);
        g_A[t] = make_float4(x0, x1, y0, y1);
        g_B[t] = make_float4(z0, z1, -w0, -w1);
    }
    if (t < CIN * WCOLS) {
        int kk = t >> 9;
        int c  = t & 511;
        g_W2[t] = (c < COUT) ? W[kk*COUT + c] : W[(kk + CIN)*COUT + (c - COUT)];
    }
    if (t < COUT) { g_sumD[t] = 0.0; g_sumsqD[t] = 0.0; }
}

// ---- knn phase 1+2: exact 21st-best score among candidates [0,2048) ----
// Stage 1: unconditional top-21 merge over [0,256) -> thr0.
// Stage 2: buffer survivors (s>thr0) of [256,2048) via predicated stores (no votes),
//          then merge buffered survivors -> exact 21st of the 2048-sample.
// Subset 21st <= full-set 21st, so thr1 is a guaranteed-valid survivor threshold.
__global__ void knn_thresh_kernel() {
    __shared__ double2 tA[KTP];
    __shared__ double2 tB[KTP];
    const int q = blockIdx.x * blockDim.x + threadIdx.x;
    const float4 me = g_cand[q];
    const unsigned long long mx = bcast2(me.x), my = bcast2(me.y), mz = bcast2(me.z);
    const float NEG = -3.0e38f;

    for (int l = threadIdx.x; l < KTP; l += blockDim.x) {
        tA[l] = ((const double2*)g_A)[l];
        tB[l] = ((const double2*)g_B)[l];
    }
    __syncthreads();

    float ss[21];
#pragma unroll
    for (int t = 0; t < 21; t++) ss[t] = NEG;

    // stage 1: candidates [0,256)
    for (int p = 0; p < 128; p += 4) {
        float s[8];
        score8(s, tA, tB, p, mx, my, mz);
#pragma unroll
        for (int u = 0; u < 8; u++) {
            float sv = (2*p + u != q) ? s[u] : NEG;
            merge21(ss, sv);
        }
    }
    const float thr0 = ss[0];

    // stage 2: candidates [256,2048) -> buffer survivors
    int cnt = 0;
    for (int p = 128; p < KTP; p += 4) {
        float s[8];
        score8(s, tA, tB, p, mx, my, mz);
        const int jb = 2*p;
#pragma unroll
        for (int u = 0; u < 8; u++) {
            int j = jb + u;
            if (s[u] > thr0 && j != q && cnt < CAP) {
                g_buf[(size_t)cnt * NP + q] =
                    ((unsigned long long)__float_as_uint(s[u]) << 32) | (unsigned)j;
                cnt++;
            }
        }
    }
    for (int m = 0; m < cnt; m++) {
        float sv = __uint_as_float((unsigned)(g_buf[(size_t)m * NP + q] >> 32));
        merge21(ss, sv);
    }
    g_thr1[q] = ss[0];
}

// ---- knn phase 3: full-scan survivor collection + exact top-20 select ----
__global__ void knn_select_kernel() {
    __shared__ double2 tA[KTP];
    __shared__ double2 tB[KTP];
    const int q = blockIdx.x * blockDim.x + threadIdx.x;
    const float4 me = g_cand[q];
    const unsigned long long mx = bcast2(me.x), my = bcast2(me.y), mz = bcast2(me.z);
    const float NEG = -3.0e38f;
    const float thr1 = g_thr1[q];

    int cnt = 0;
    for (int tb = 0; tb < NP/2; tb += KTP) {
        __syncthreads();
        for (int l = threadIdx.x; l < KTP; l += blockDim.x) {
            tA[l] = ((const double2*)g_A)[tb + l];
            tB[l] = ((const double2*)g_B)[tb + l];
        }
        __syncthreads();
        for (int p = 0; p < KTP; p += 4) {
            float s[8];
            score8(s, tA, tB, p, mx, my, mz);
            const int jb = 2*(tb + p);
#pragma unroll
            for (int u = 0; u < 8; u++) {
                int j = jb + u;
                if (s[u] > thr1 && j != q && cnt < CAP) {   // predicated, voteless
                    g_buf[(size_t)cnt * NP + q] =
                        ((unsigned long long)__float_as_uint(s[u]) << 32) | (unsigned)j;
                    cnt++;
                }
            }
        }
    }

    // exact 21st among survivors (NEG if cnt <= 20)
    float tt[21];
#pragma unroll
    for (int t = 0; t < 21; t++) tt[t] = NEG;
    for (int m = 0; m < cnt; m++) {
        float sv = __uint_as_float((unsigned)(g_buf[(size_t)m * NP + q] >> 32));
        merge21(tt, sv);
    }
    const float t21 = tt[0];

    int out = 0;
    for (int m = 0; m < cnt && out < KK; m++) {          // strictly above 21st
        unsigned long long e = g_buf[(size_t)m * NP + q];
        float sv = __uint_as_float((unsigned)(e >> 32));
        if (sv > t21) g_knn[q*KK + (out++)] = (int)(e & 0xffffffffu);
    }
    for (int m = 0; m < cnt && out < KK; m++) {          // ties at 21st, ascending index
        unsigned long long e = g_buf[(size_t)m * NP + q];
        float sv = __uint_as_float((unsigned)(e >> 32));
        if (sv == t21) g_knn[q*KK + (out++)] = (int)(e & 0xffffffffu);
    }
    if (out < KK) {  // exact-tie-at-thr1 fallback: essentially never taken
        for (int j = 0; j < NP && out < KK; j++) {
            if (j == q) continue;
            float4 c = g_cand[j];
            float sv = fmaf(me.x, c.x, fmaf(me.y, c.y, fmaf(me.z, c.z, -c.w)));
            if (sv == thr1) g_knn[q*KK + (out++)] = j;
        }
    }
}

// ---- SGEMM: AB[16384,512] = X[16384,128] @ W2[128,512]  (+bias on cols<256) ----
__global__ void gemm_kernel(const float* __restrict__ X, const float* __restrict__ bias) {
    __shared__ float As[8][128];
    __shared__ float Bs[8][128];
    const int tid = threadIdx.x;
    const int m0 = blockIdx.y * 128;
    const int n0 = blockIdx.x * 128;
    const int tx = tid & 15;
    const int ty = tid >> 4;
    const int lam = tid >> 1;
    const int lak = (tid & 1) * 4;
    const int lbr = tid >> 5;
    const int lbc = (tid & 31) * 4;

    float acc[8][8];
#pragma unroll
    for (int i = 0; i < 8; i++)
#pragma unroll
        for (int j = 0; j < 8; j++) acc[i][j] = 0.0f;

    for (int kb = 0; kb < CIN; kb += 8) {
        float4 av = *(const float4*)&X[(size_t)(m0 + lam)*CIN + kb + lak];
        float4 bv = *(const float4*)&g_W2[(kb + lbr)*WCOLS + n0 + lbc];
        __syncthreads();
        As[lak+0][lam] = av.x;
        As[lak+1][lam] = av.y;
        As[lak+2][lam] = av.z;
        As[lak+3][lam] = av.w;
        *(float4*)&Bs[lbr][lbc] = bv;
        __syncthreads();
#pragma unroll
        for (int k = 0; k < 8; k++) {
            float a[8], bb[8];
            *(float4*)&a[0]  = *(const float4*)&As[k][ty*8];
            *(float4*)&a[4]  = *(const float4*)&As[k][ty*8 + 4];
            *(float4*)&bb[0] = *(const float4*)&Bs[k][tx*8];
            *(float4*)&bb[4] = *(const float4*)&Bs[k][tx*8 + 4];
#pragma unroll
            for (int i = 0; i < 8; i++)
#pragma unroll
                for (int j = 0; j < 8; j++)
                    acc[i][j] = fmaf(a[i], bb[j], acc[i][j]);
        }
    }
    const bool addb = (n0 < COUT);
#pragma unroll
    for (int i = 0; i < 8; i++) {
        int row = m0 + ty*8 + i;
#pragma unroll
        for (int j = 0; j < 8; j += 4) {
            int col = n0 + tx*8 + j;
            float4 v;
            v.x = acc[i][j+0] + (addb ? bias[col+0] : 0.0f);
            v.y = acc[i][j+1] + (addb ? bias[col+1] : 0.0f);
            v.z = acc[i][j+2] + (addb ? bias[col+2] : 0.0f);
            v.w = acc[i][j+3] + (addb ? bias[col+3] : 0.0f);
            *(float4*)&g_AB[(size_t)row*WCOLS + col] = v;
        }
    }
}

// ---- fused edge pass: per (i,c) extreme over neighbors + channel sum/sumsq ----
__global__ void edge_kernel(const float* __restrict__ gamma) {
    const int c  = threadIdx.x;
    const int i0 = blockIdx.x * QPB;
    const bool useMax = (gamma[c] >= 0.0f);
    float psum = 0.0f, psumsq = 0.0f;
    for (int g = 0; g < QPB; g++) {
        const int i = i0 + g;
        const float a = g_AB[(size_t)i*WCOLS + c];
        float best = useMax ? -3.0e38f : 3.0e38f;
#pragma unroll
        for (int k = 0; k < KK; k++) {
            int j = g_knn[i*KK + k];
            float h = a + g_AB[(size_t)j*WCOLS + COUT + c];
            psum += h;
            psumsq = fmaf(h, h, psumsq);
            best = useMax ? fmaxf(best, h) : fminf(best, h);
        }
        g_sel[(size_t)i*COUT + c] = best;
    }
    atomicAdd(&g_sumD[c], (double)psum);
    atomicAdd(&g_sumsqD[c], (double)psumsq);
}

// ---- BN stats -> per-channel scale/shift ----
__global__ void finalize_kernel(const float* __restrict__ gamma, const float* __restrict__ beta) {
    int c = threadIdx.x;
    const double inv = 1.0 / (double)(NP * KK);
    double m  = g_sumD[c] * inv;
    double v  = g_sumsqD[c] * inv - m*m;
    float sc = gamma[c] * rsqrtf((float)v + 1e-5f);
    g_scale[c] = sc;
    g_shift[c] = beta[c] - (float)m * sc;
}

// ---- epilogue: normalize selected extreme + LeakyReLU ----
__global__ void out_kernel(float* __restrict__ out) {
    int t = blockIdx.x * blockDim.x + threadIdx.x;
    int c = t & (COUT - 1);
    float h = fmaf(g_sel[t], g_scale[c], g_shift[c]);
    out[t] = (h >= 0.0f) ? h : 0.2f*h;
}

extern "C" void kernel_launch(void* const* d_in, const int* in_sizes, int n_in,
                              void* d_out, int out_size) {
    const float* pos   = (const float*)d_in[0];
    const float* x     = (const float*)d_in[1];
    const float* W     = (const float*)d_in[2];
    const float* b     = (const float*)d_in[3];
    const float* gamma = (const float*)d_in[4];
    const float* beta  = (const float*)d_in[5];
    float* out = (float*)d_out;

    prep_kernel<<<256, 256>>>(pos, W);                       // launch 0
    gemm_kernel<<<dim3(WCOLS / 128, NP / 128), 256>>>(x, b); // launch 1
    knn_thresh_kernel<<<NP / 64, 64>>>();                    // launch 2
    knn_select_kernel<<<NP / 64, 64>>>();                    // launch 3 (ncu slot)
    edge_kernel<<<NP / QPB, 256>>>(gamma);                   // launch 4
    finalize_kernel<<<1, COUT>>>(gamma, beta);               // launch 5
    out_kernel<<<(NP * COUT) / 256, 256>>>(out);             // launch 6
}